// round 2
// baseline (speedup 1.0000x reference)
#include <cuda_runtime.h>
#include <cstdint>

#define NN   100000
#define RR   8
#define EE   1600000
#define F0   128
#define F1   64
#define F2   32
#define LDO1 576   /* 8*64 + 64 (root) */
#define LDO2 288   /* 8*32 + 32 (root) */

// ---------------- scratch (device globals: allocation-free) ----------------
__device__ float g_H[(size_t)NN * LDO1];   // 230 MB, reused as H2 [NN,288]
__device__ float g_out1[NN * F1];          // layer-1 output
__device__ int   g_cnt[NN * RR];
__device__ float g_invc[NN * RR];
__device__ int   g_rowptr[NN + 1];
__device__ int   g_cursor[NN];
__device__ int   g_csr[EE];                // packed src*8+rel
__device__ int   g_blocksums[256];
__device__ int   g_is64[2];                // dtype flags: edge_index, edge_type

// ---------------- dtype detection ----------------
// int64 little-endian positive values => every odd 32-bit word is zero.
// int32 values (uniform over [0,1e5) / [0,8)) => some odd word nonzero w.p. ~1.
__global__ void k_detect(const int* __restrict__ ei, const int* __restrict__ et) {
    __shared__ int nz0, nz1;
    if (threadIdx.x == 0) { nz0 = 0; nz1 = 0; }
    __syncthreads();
    for (int i = threadIdx.x; i < 1024; i += blockDim.x) {
        if (ei[2 * i + 1] != 0) atomicOr(&nz0, 1);
        if (et[2 * i + 1] != 0) atomicOr(&nz1, 1);
    }
    __syncthreads();
    if (threadIdx.x == 0) { g_is64[0] = nz0 ? 0 : 1; g_is64[1] = nz1 ? 0 : 1; }
}

__device__ __forceinline__ int readIdx(const void* p, int is64, int i) {
    return is64 ? (int)((const long long*)p)[i] : ((const int*)p)[i];
}

// ---------------- CSR build ----------------
__global__ void k_zero_cnt() {
    int i = blockIdx.x * blockDim.x + threadIdx.x;
    if (i < NN * RR) g_cnt[i] = 0;
}

__global__ void k_count(const void* __restrict__ ei, const void* __restrict__ et) {
    int e = blockIdx.x * blockDim.x + threadIdx.x;
    if (e >= EE) return;
    int dst = readIdx(ei, g_is64[0], EE + e);
    int rel = readIdx(et, g_is64[1], e) & 7;
    if ((unsigned)dst >= NN) dst = 0;
    atomicAdd(&g_cnt[dst * RR + rel], 1);
}

__global__ void k_scan1() {
    __shared__ int s[512];
    int t = threadIdx.x;
    int i = blockIdx.x * 512 + t;
    int d = 0;
    if (i < NN) {
        #pragma unroll
        for (int r = 0; r < RR; r++) d += g_cnt[i * RR + r];
    }
    s[t] = d;
    __syncthreads();
    for (int off = 256; off > 0; off >>= 1) {
        if (t < off) s[t] += s[t + off];
        __syncthreads();
    }
    if (t == 0) g_blocksums[blockIdx.x] = s[0];
}

__global__ void k_scan2(int nblk) {
    if (threadIdx.x == 0) {
        int run = 0;
        for (int b = 0; b < nblk; b++) { int v = g_blocksums[b]; g_blocksums[b] = run; run += v; }
    }
}

__global__ void k_scan3() {
    __shared__ int s[512];
    int t = threadIdx.x;
    int i = blockIdx.x * 512 + t;
    int d = 0;
    if (i < NN) {
        #pragma unroll
        for (int r = 0; r < RR; r++) d += g_cnt[i * RR + r];
    }
    s[t] = d;
    __syncthreads();
    // Hillis-Steele inclusive scan
    for (int off = 1; off < 512; off <<= 1) {
        int v = (t >= off) ? s[t - off] : 0;
        __syncthreads();
        s[t] += v;
        __syncthreads();
    }
    if (i < NN) {
        int rp = g_blocksums[blockIdx.x] + s[t] - d;   // exclusive
        g_rowptr[i] = rp;
        g_cursor[i] = rp;
        #pragma unroll
        for (int r = 0; r < RR; r++) {
            int c = g_cnt[i * RR + r];
            g_invc[i * RR + r] = 1.0f / (float)(c > 0 ? c : 1);
        }
    }
    if (blockIdx.x == 0 && t == 0) g_rowptr[NN] = EE;
}

__global__ void k_scatter(const void* __restrict__ ei, const void* __restrict__ et) {
    int e = blockIdx.x * blockDim.x + threadIdx.x;
    if (e >= EE) return;
    int src = readIdx(ei, g_is64[0], e);
    int dst = readIdx(ei, g_is64[0], EE + e);
    int rel = readIdx(et, g_is64[1], e) & 7;
    if ((unsigned)src >= NN) src = 0;
    if ((unsigned)dst >= NN) dst = 0;
    int pos = atomicAdd(&g_cursor[dst], 1);
    if ((unsigned)pos < EE) g_csr[pos] = src * RR + rel;
}

// ---------------- tf32 GEMM: H = A @ [W_0 .. W_7 | root] ----------------
__device__ __forceinline__ float to_tf32(float x) {
    uint32_t u;
    asm("cvt.rna.tf32.f32 %0, %1;" : "=r"(u) : "f"(x));
    return __uint_as_float(u);
}

__device__ __forceinline__ void mma_tf32(float* c, const uint32_t* a, const uint32_t* b) {
    asm volatile(
        "mma.sync.aligned.m16n8k8.row.col.f32.tf32.tf32.f32 "
        "{%0,%1,%2,%3},{%4,%5,%6,%7},{%8,%9},{%0,%1,%2,%3};"
        : "+f"(c[0]), "+f"(c[1]), "+f"(c[2]), "+f"(c[3])
        : "r"(a[0]), "r"(a[1]), "r"(a[2]), "r"(a[3]), "r"(b[0]), "r"(b[1]));
}

// BM=64, 8 warps as 2(m) x 4(n). Warp m-tile 32 rows (2 x m16), n-tile BN/4.
// K staged in 64-wide chunks; static shared memory only (<= 36 KB).
template <int KT, int BN, bool A_IS_OUT1>
__global__ void __launch_bounds__(256) k_gemm(
    const float* __restrict__ Aext,
    const float* __restrict__ Wrel,   // [8][KT][BN]
    const float* __restrict__ Wroot)  // [KT][BN]
{
    constexpr int BM = 64;
    constexpr int KC = 64;
    constexpr int AS = KC + 4;       // A smem stride
    constexpr int BS = BN + 8;       // B smem stride (conflict-free frag loads)
    constexpr int WN = BN / 4;
    constexpr int NF = WN / 8;
    constexpr int LDO = 9 * BN;
    constexpr int NCH = KT / KC;

    __shared__ float As[BM * AS];
    __shared__ float Bs[KC * BS];

    const float* A = A_IS_OUT1 ? (const float*)g_out1 : Aext;
    int tid = threadIdx.x;
    int m0 = blockIdx.x * BM;
    int nt = blockIdx.y;             // 0..7 relations, 8 = root
    const float* Bsrc = (nt < 8) ? (Wrel + (size_t)nt * KT * BN) : Wroot;

    int wid = tid >> 5, lane = tid & 31;
    int wm = wid & 1, wn = wid >> 1;
    int grp = lane >> 2, tig = lane & 3;

    float c[2][NF][4];
    #pragma unroll
    for (int mf = 0; mf < 2; mf++)
        #pragma unroll
        for (int nf = 0; nf < NF; nf++)
            #pragma unroll
            for (int q = 0; q < 4; q++) c[mf][nf][q] = 0.f;

    for (int ch = 0; ch < NCH; ch++) {
        int k0 = ch * KC;
        // stage A chunk [BM][KC]
        for (int idx = tid; idx < BM * KC / 4; idx += 256) {
            int r  = idx / (KC / 4);
            int c4 = (idx % (KC / 4)) * 4;
            float4 v = make_float4(0.f, 0.f, 0.f, 0.f);
            if (m0 + r < NN) v = *(const float4*)(A + (size_t)(m0 + r) * KT + k0 + c4);
            v.x = to_tf32(v.x); v.y = to_tf32(v.y); v.z = to_tf32(v.z); v.w = to_tf32(v.w);
            *(float4*)(As + r * AS + c4) = v;
        }
        // stage B chunk [KC][BN]
        for (int idx = tid; idx < KC * BN / 4; idx += 256) {
            int k  = idx / (BN / 4);
            int c4 = (idx % (BN / 4)) * 4;
            float4 v = *(const float4*)(Bsrc + (size_t)(k0 + k) * BN + c4);
            v.x = to_tf32(v.x); v.y = to_tf32(v.y); v.z = to_tf32(v.z); v.w = to_tf32(v.w);
            *(float4*)(Bs + k * BS + c4) = v;
        }
        __syncthreads();

        #pragma unroll
        for (int kk = 0; kk < KC / 8; kk++) {
            int kb = kk * 8;
            uint32_t a[2][4];
            #pragma unroll
            for (int mf = 0; mf < 2; mf++) {
                const float* p = As + (wm * 32 + mf * 16 + grp) * AS + kb + tig;
                a[mf][0] = __float_as_uint(p[0]);
                a[mf][1] = __float_as_uint(p[8 * AS]);
                a[mf][2] = __float_as_uint(p[4]);
                a[mf][3] = __float_as_uint(p[8 * AS + 4]);
            }
            uint32_t b[NF][2];
            #pragma unroll
            for (int nf = 0; nf < NF; nf++) {
                const float* p = Bs + (kb + tig) * BS + wn * WN + nf * 8 + grp;
                b[nf][0] = __float_as_uint(p[0]);
                b[nf][1] = __float_as_uint(p[4 * BS]);
            }
            #pragma unroll
            for (int mf = 0; mf < 2; mf++)
                #pragma unroll
                for (int nf = 0; nf < NF; nf++)
                    mma_tf32(c[mf][nf], a[mf], b[nf]);
        }
        __syncthreads();
    }

    // store
    #pragma unroll
    for (int mf = 0; mf < 2; mf++)
        #pragma unroll
        for (int nf = 0; nf < NF; nf++) {
            int row = m0 + wm * 32 + mf * 16 + grp;
            int col = nt * BN + wn * WN + nf * 8 + tig * 2;
            float* p = g_H + (size_t)row * LDO + col;
            if (row < NN)     { p[0] = c[mf][nf][0]; p[1] = c[mf][nf][1]; }
            if (row + 8 < NN) { p[(size_t)8 * LDO] = c[mf][nf][2]; p[(size_t)8 * LDO + 1] = c[mf][nf][3]; }
        }
}

// ---------------- aggregation (warp per dst node, no atomics) ----------------
__global__ void __launch_bounds__(256) k_agg1(const float* __restrict__ bias1) {
    int gw = (blockIdx.x * blockDim.x + threadIdx.x) >> 5;
    int lane = threadIdx.x & 31;
    if (gw >= NN) return;
    int beg = g_rowptr[gw], end = g_rowptr[gw + 1];
    float invc = (lane < RR) ? g_invc[gw * RR + lane] : 0.f;
    float acc0 = 0.f, acc1 = 0.f;
    int i = beg;
    while (i < end) {
        int nb = min(32, end - i);
        int id = (lane < nb) ? g_csr[i + lane] : 0;
        int k = 0;
        for (; k + 2 <= nb; k += 2) {
            int e0 = __shfl_sync(0xffffffffu, id, k);
            int e1 = __shfl_sync(0xffffffffu, id, k + 1);
            float s0 = __shfl_sync(0xffffffffu, invc, e0 & 7);
            float s1 = __shfl_sync(0xffffffffu, invc, e1 & 7);
            const float* h0 = g_H + (size_t)(e0 >> 3) * LDO1 + (e0 & 7) * F1;
            const float* h1 = g_H + (size_t)(e1 >> 3) * LDO1 + (e1 & 7) * F1;
            float v00 = h0[lane], v01 = h0[lane + 32];
            float v10 = h1[lane], v11 = h1[lane + 32];
            acc0 += v00 * s0; acc1 += v01 * s0;
            acc0 += v10 * s1; acc1 += v11 * s1;
        }
        if (k < nb) {
            int e0 = __shfl_sync(0xffffffffu, id, k);
            float s0 = __shfl_sync(0xffffffffu, invc, e0 & 7);
            const float* h0 = g_H + (size_t)(e0 >> 3) * LDO1 + (e0 & 7) * F1;
            acc0 += h0[lane] * s0;
            acc1 += h0[lane + 32] * s0;
        }
        i += nb;
    }
    const float* hr = g_H + (size_t)gw * LDO1 + RR * F1;   // root block
    float o0 = bias1[lane]      + hr[lane]      + acc0;
    float o1 = bias1[lane + 32] + hr[lane + 32] + acc1;
    g_out1[gw * F1 + lane]      = fmaxf(o0, 0.f);
    g_out1[gw * F1 + 32 + lane] = fmaxf(o1, 0.f);
}

__global__ void __launch_bounds__(256) k_agg2(const float* __restrict__ bias2,
                                              float* __restrict__ out) {
    int gw = (blockIdx.x * blockDim.x + threadIdx.x) >> 5;
    int lane = threadIdx.x & 31;
    if (gw >= NN) return;
    int beg = g_rowptr[gw], end = g_rowptr[gw + 1];
    float invc = (lane < RR) ? g_invc[gw * RR + lane] : 0.f;
    float acc = 0.f;
    int i = beg;
    while (i < end) {
        int nb = min(32, end - i);
        int id = (lane < nb) ? g_csr[i + lane] : 0;
        int k = 0;
        for (; k + 2 <= nb; k += 2) {
            int e0 = __shfl_sync(0xffffffffu, id, k);
            int e1 = __shfl_sync(0xffffffffu, id, k + 1);
            float s0 = __shfl_sync(0xffffffffu, invc, e0 & 7);
            float s1 = __shfl_sync(0xffffffffu, invc, e1 & 7);
            float v0 = g_H[(size_t)(e0 >> 3) * LDO2 + (e0 & 7) * F2 + lane];
            float v1 = g_H[(size_t)(e1 >> 3) * LDO2 + (e1 & 7) * F2 + lane];
            acc += v0 * s0;
            acc += v1 * s1;
        }
        if (k < nb) {
            int e0 = __shfl_sync(0xffffffffu, id, k);
            float s0 = __shfl_sync(0xffffffffu, invc, e0 & 7);
            acc += g_H[(size_t)(e0 >> 3) * LDO2 + (e0 & 7) * F2 + lane] * s0;
        }
        i += nb;
    }
    float z = bias2[lane] + g_H[(size_t)gw * LDO2 + RR * F2 + lane] + acc;
    out[gw * F2 + lane] = 1.0f / (1.0f + __expf(-z));
}

// ---------------- launch ----------------
extern "C" void kernel_launch(void* const* d_in, const int* in_sizes, int n_in,
                              void* d_out, int out_size) {
    const void*  ei    = d_in[0];
    const void*  et    = d_in[1];
    const float* emb   = (const float*)d_in[2];
    const float* W1    = (const float*)d_in[3];
    const float* root1 = (const float*)d_in[4];
    const float* bias1 = (const float*)d_in[5];
    const float* W2    = (const float*)d_in[6];
    const float* root2 = (const float*)d_in[7];
    const float* bias2 = (const float*)d_in[8];
    float*       out   = (float*)d_out;

    // dtype detection + CSR build
    k_detect<<<1, 256>>>((const int*)ei, (const int*)et);
    k_zero_cnt<<<(NN * RR + 255) / 256, 256>>>();
    k_count<<<(EE + 255) / 256, 256>>>(ei, et);
    k_scan1<<<196, 512>>>();
    k_scan2<<<1, 32>>>(196);
    k_scan3<<<196, 512>>>();
    k_scatter<<<(EE + 255) / 256, 256>>>(ei, et);

    // layer 1
    dim3 g1((NN + 63) / 64, 9);
    k_gemm<128, 64, false><<<g1, 256>>>(emb, W1, root1);
    k_agg1<<<(NN + 7) / 8, 256>>>(bias1);

    // layer 2
    dim3 g2((NN + 63) / 64, 9);
    k_gemm<64, 32, true><<<g2, 256>>>(nullptr, W2, root2);
    k_agg2<<<(NN + 7) / 8, 256>>>(bias2, out);
}

// round 3
// speedup vs baseline: 1.0316x; 1.0316x over previous
#include <cuda_runtime.h>
#include <cstdint>

#define NN   100000
#define RR   8
#define EE   1600000
#define F0   128
#define F1   64
#define F2   32
#define LDO1 576   /* 8*64 + 64 (root) */
#define LDO2 288   /* 8*32 + 32 (root) */

// ---------------- scratch (device globals: allocation-free) ----------------
__device__ float g_H[(size_t)NN * LDO1];   // 230 MB, reused as H2 [NN,288]
__device__ float g_out1[NN * F1];          // layer-1 output
__device__ int   g_cnt[NN * RR];
__device__ float g_invc[NN * RR];
__device__ int   g_rowptr[NN + 1];
__device__ int   g_cursor[NN];
__device__ int   g_csr[EE];                // packed src*8+rel
__device__ int   g_blocksums[256];
__device__ int   g_is64[2];                // dtype flags: edge_index, edge_type

// ---------------- dtype detection ----------------
__global__ void k_detect(const int* __restrict__ ei, const int* __restrict__ et) {
    __shared__ int nz0, nz1;
    if (threadIdx.x == 0) { nz0 = 0; nz1 = 0; }
    __syncthreads();
    for (int i = threadIdx.x; i < 1024; i += blockDim.x) {
        if (ei[2 * i + 1] != 0) atomicOr(&nz0, 1);
        if (et[2 * i + 1] != 0) atomicOr(&nz1, 1);
    }
    __syncthreads();
    if (threadIdx.x == 0) { g_is64[0] = nz0 ? 0 : 1; g_is64[1] = nz1 ? 0 : 1; }
}

__device__ __forceinline__ int readIdx(const void* p, int is64, int i) {
    return is64 ? (int)((const long long*)p)[i] : ((const int*)p)[i];
}

// ---------------- CSR build ----------------
__global__ void k_zero_cnt() {
    int i = blockIdx.x * blockDim.x + threadIdx.x;
    if (i < NN * RR) g_cnt[i] = 0;
}

__global__ void k_count(const void* __restrict__ ei, const void* __restrict__ et) {
    int e = blockIdx.x * blockDim.x + threadIdx.x;
    if (e >= EE) return;
    int dst = readIdx(ei, g_is64[0], EE + e);
    int rel = readIdx(et, g_is64[1], e) & 7;
    if ((unsigned)dst >= NN) dst = 0;
    atomicAdd(&g_cnt[dst * RR + rel], 1);
}

__global__ void k_scan1() {
    __shared__ int s[512];
    int t = threadIdx.x;
    int i = blockIdx.x * 512 + t;
    int d = 0;
    if (i < NN) {
        #pragma unroll
        for (int r = 0; r < RR; r++) d += g_cnt[i * RR + r];
    }
    s[t] = d;
    __syncthreads();
    for (int off = 256; off > 0; off >>= 1) {
        if (t < off) s[t] += s[t + off];
        __syncthreads();
    }
    if (t == 0) g_blocksums[blockIdx.x] = s[0];
}

__global__ void k_scan2(int nblk) {
    if (threadIdx.x == 0) {
        int run = 0;
        for (int b = 0; b < nblk; b++) { int v = g_blocksums[b]; g_blocksums[b] = run; run += v; }
    }
}

__global__ void k_scan3() {
    __shared__ int s[512];
    int t = threadIdx.x;
    int i = blockIdx.x * 512 + t;
    int d = 0;
    if (i < NN) {
        #pragma unroll
        for (int r = 0; r < RR; r++) d += g_cnt[i * RR + r];
    }
    s[t] = d;
    __syncthreads();
    for (int off = 1; off < 512; off <<= 1) {
        int v = (t >= off) ? s[t - off] : 0;
        __syncthreads();
        s[t] += v;
        __syncthreads();
    }
    if (i < NN) {
        int rp = g_blocksums[blockIdx.x] + s[t] - d;   // exclusive
        g_rowptr[i] = rp;
        g_cursor[i] = rp;
        #pragma unroll
        for (int r = 0; r < RR; r++) {
            int c = g_cnt[i * RR + r];
            g_invc[i * RR + r] = 1.0f / (float)(c > 0 ? c : 1);
        }
    }
    if (blockIdx.x == 0 && t == 0) g_rowptr[NN] = EE;
}

__global__ void k_scatter(const void* __restrict__ ei, const void* __restrict__ et) {
    int e = blockIdx.x * blockDim.x + threadIdx.x;
    if (e >= EE) return;
    int src = readIdx(ei, g_is64[0], e);
    int dst = readIdx(ei, g_is64[0], EE + e);
    int rel = readIdx(et, g_is64[1], e) & 7;
    if ((unsigned)src >= NN) src = 0;
    if ((unsigned)dst >= NN) dst = 0;
    int pos = atomicAdd(&g_cursor[dst], 1);
    if ((unsigned)pos < EE) g_csr[pos] = src * RR + rel;
}

// ---------------- tf32 GEMM: H = A @ [W_0 .. W_7 | root] ----------------
__device__ __forceinline__ float to_tf32(float x) {
    uint32_t u;
    asm("cvt.rna.tf32.f32 %0, %1;" : "=r"(u) : "f"(x));
    return __uint_as_float(u);
}

__device__ __forceinline__ void mma_tf32(float* c, const uint32_t* a, const uint32_t* b) {
    asm volatile(
        "mma.sync.aligned.m16n8k8.row.col.f32.tf32.tf32.f32 "
        "{%0,%1,%2,%3},{%4,%5,%6,%7},{%8,%9},{%0,%1,%2,%3};"
        : "+f"(c[0]), "+f"(c[1]), "+f"(c[2]), "+f"(c[3])
        : "r"(a[0]), "r"(a[1]), "r"(a[2]), "r"(a[3]), "r"(b[0]), "r"(b[1]));
}

// BM=128, KC=32. 8 warps as WARPM(m) x (8/WARPM)(n).
// n-tile BN covers BN/FOUT relation blocks (relations contiguous in output).
template <int KT, int FOUT, int BN, int WARPM, bool A_IS_OUT1>
__global__ void __launch_bounds__(256) k_gemm(
    const float* __restrict__ Aext,
    const float* __restrict__ Wrel,   // [8][KT][FOUT]
    const float* __restrict__ Wroot)  // [KT][FOUT]
{
    constexpr int BM = 128, KC = 32;
    constexpr int AS = KC + 4;
    constexpr int BS = BN + 8;
    constexpr int WARPN = 8 / WARPM;
    constexpr int WMROWS = BM / WARPM;
    constexpr int MF = WMROWS / 16;
    constexpr int WN = BN / WARPN;
    constexpr int NF = WN / 8;
    constexpr int LDO = 9 * FOUT;
    constexpr int NCH = KT / KC;

    __shared__ float As[BM * AS];
    __shared__ float Bs[KC * BS];

    const float* A = A_IS_OUT1 ? (const float*)g_out1 : Aext;
    int tid = threadIdx.x;
    int m0 = blockIdx.x * BM;
    int n0 = blockIdx.y * BN;

    int wid = tid >> 5, lane = tid & 31;
    int wm = wid % WARPM, wn = wid / WARPM;
    int grp = lane >> 2, tig = lane & 3;

    float c[MF][NF][4];
    #pragma unroll
    for (int mf = 0; mf < MF; mf++)
        #pragma unroll
        for (int nf = 0; nf < NF; nf++)
            #pragma unroll
            for (int q = 0; q < 4; q++) c[mf][nf][q] = 0.f;

    for (int ch = 0; ch < NCH; ch++) {
        int k0 = ch * KC;
        // stage A chunk [BM][KC]
        #pragma unroll
        for (int idx = tid; idx < BM * KC / 4; idx += 256) {
            int r  = idx >> 3;            // KC/4 = 8 float4 per row
            int c4 = (idx & 7) * 4;
            float4 v = make_float4(0.f, 0.f, 0.f, 0.f);
            if (m0 + r < NN) v = *(const float4*)(A + (size_t)(m0 + r) * KT + k0 + c4);
            v.x = to_tf32(v.x); v.y = to_tf32(v.y); v.z = to_tf32(v.z); v.w = to_tf32(v.w);
            *(float4*)(As + r * AS + c4) = v;
        }
        // stage B chunk [KC][BN] (piecewise over relation blocks; FOUT%4==0 so
        // a float4 never straddles a relation boundary)
        #pragma unroll
        for (int idx = tid; idx < KC * BN / 4; idx += 256) {
            int k  = idx / (BN / 4);
            int c4 = (idx % (BN / 4)) * 4;
            int gc = n0 + c4;
            int rel = gc / FOUT;
            int within = gc % FOUT;
            const float* src = (rel < 8)
                ? (Wrel + ((size_t)rel * KT + k0 + k) * FOUT + within)
                : (Wroot + (size_t)(k0 + k) * FOUT + within);
            float4 v = *(const float4*)src;
            v.x = to_tf32(v.x); v.y = to_tf32(v.y); v.z = to_tf32(v.z); v.w = to_tf32(v.w);
            *(float4*)(Bs + k * BS + c4) = v;
        }
        __syncthreads();

        #pragma unroll
        for (int kk = 0; kk < KC / 8; kk++) {
            int kb = kk * 8;
            uint32_t a[MF][4];
            #pragma unroll
            for (int mf = 0; mf < MF; mf++) {
                const float* p = As + (wm * WMROWS + mf * 16 + grp) * AS + kb + tig;
                a[mf][0] = __float_as_uint(p[0]);
                a[mf][1] = __float_as_uint(p[8 * AS]);
                a[mf][2] = __float_as_uint(p[4]);
                a[mf][3] = __float_as_uint(p[8 * AS + 4]);
            }
            uint32_t b[NF][2];
            #pragma unroll
            for (int nf = 0; nf < NF; nf++) {
                const float* p = Bs + (kb + tig) * BS + wn * WN + nf * 8 + grp;
                b[nf][0] = __float_as_uint(p[0]);
                b[nf][1] = __float_as_uint(p[4 * BS]);
            }
            #pragma unroll
            for (int mf = 0; mf < MF; mf++)
                #pragma unroll
                for (int nf = 0; nf < NF; nf++)
                    mma_tf32(c[mf][nf], a[mf], b[nf]);
        }
        __syncthreads();
    }

    // store
    #pragma unroll
    for (int mf = 0; mf < MF; mf++)
        #pragma unroll
        for (int nf = 0; nf < NF; nf++) {
            int row = m0 + wm * WMROWS + mf * 16 + grp;
            int col = n0 + wn * WN + nf * 8 + tig * 2;
            float* p = g_H + (size_t)row * LDO + col;
            if (row < NN)     { p[0] = c[mf][nf][0]; p[1] = c[mf][nf][1]; }
            if (row + 8 < NN) { p[(size_t)8 * LDO] = c[mf][nf][2]; p[(size_t)8 * LDO + 1] = c[mf][nf][3]; }
        }
}

// ---------------- aggregation (warp per dst node, no atomics) ----------------
__global__ void __launch_bounds__(256) k_agg1(const float* __restrict__ bias1) {
    int gw = (blockIdx.x * blockDim.x + threadIdx.x) >> 5;
    int lane = threadIdx.x & 31;
    if (gw >= NN) return;
    int beg = g_rowptr[gw], end = g_rowptr[gw + 1];
    float invc = (lane < RR) ? g_invc[gw * RR + lane] : 0.f;
    const float2* Hp = (const float2*)g_H;   // row stride 288 float2, rel stride 32
    float acc0 = 0.f, acc1 = 0.f;
    int i = beg;
    while (i < end) {
        int nb = min(32, end - i);
        int id = (lane < nb) ? g_csr[i + lane] : 0;
        int k = 0;
        for (; k + 4 <= nb; k += 4) {
            int e0 = __shfl_sync(0xffffffffu, id, k);
            int e1 = __shfl_sync(0xffffffffu, id, k + 1);
            int e2 = __shfl_sync(0xffffffffu, id, k + 2);
            int e3 = __shfl_sync(0xffffffffu, id, k + 3);
            float s0 = __shfl_sync(0xffffffffu, invc, e0 & 7);
            float s1 = __shfl_sync(0xffffffffu, invc, e1 & 7);
            float s2 = __shfl_sync(0xffffffffu, invc, e2 & 7);
            float s3 = __shfl_sync(0xffffffffu, invc, e3 & 7);
            float2 v0 = __ldg(&Hp[(size_t)(e0 >> 3) * 288 + (e0 & 7) * 32 + lane]);
            float2 v1 = __ldg(&Hp[(size_t)(e1 >> 3) * 288 + (e1 & 7) * 32 + lane]);
            float2 v2 = __ldg(&Hp[(size_t)(e2 >> 3) * 288 + (e2 & 7) * 32 + lane]);
            float2 v3 = __ldg(&Hp[(size_t)(e3 >> 3) * 288 + (e3 & 7) * 32 + lane]);
            acc0 += v0.x * s0 + v1.x * s1 + v2.x * s2 + v3.x * s3;
            acc1 += v0.y * s0 + v1.y * s1 + v2.y * s2 + v3.y * s3;
        }
        for (; k < nb; k++) {
            int e0 = __shfl_sync(0xffffffffu, id, k);
            float s0 = __shfl_sync(0xffffffffu, invc, e0 & 7);
            float2 v0 = __ldg(&Hp[(size_t)(e0 >> 3) * 288 + (e0 & 7) * 32 + lane]);
            acc0 += v0.x * s0;
            acc1 += v0.y * s0;
        }
        i += nb;
    }
    float2 rt = Hp[(size_t)gw * 288 + 256 + lane];      // root block (cols 512..575)
    float2 bs = ((const float2*)bias1)[lane];
    float o0 = bs.x + rt.x + acc0;
    float o1 = bs.y + rt.y + acc1;
    ((float2*)g_out1)[gw * 32 + lane] = make_float2(fmaxf(o0, 0.f), fmaxf(o1, 0.f));
}

__global__ void __launch_bounds__(256) k_agg2(const float* __restrict__ bias2,
                                              float* __restrict__ out) {
    int gw = (blockIdx.x * blockDim.x + threadIdx.x) >> 5;
    int lane = threadIdx.x & 31;
    if (gw >= NN) return;
    int beg = g_rowptr[gw], end = g_rowptr[gw + 1];
    float invc = (lane < RR) ? g_invc[gw * RR + lane] : 0.f;
    float acc = 0.f;
    int i = beg;
    while (i < end) {
        int nb = min(32, end - i);
        int id = (lane < nb) ? g_csr[i + lane] : 0;
        int k = 0;
        for (; k + 4 <= nb; k += 4) {
            int e0 = __shfl_sync(0xffffffffu, id, k);
            int e1 = __shfl_sync(0xffffffffu, id, k + 1);
            int e2 = __shfl_sync(0xffffffffu, id, k + 2);
            int e3 = __shfl_sync(0xffffffffu, id, k + 3);
            float s0 = __shfl_sync(0xffffffffu, invc, e0 & 7);
            float s1 = __shfl_sync(0xffffffffu, invc, e1 & 7);
            float s2 = __shfl_sync(0xffffffffu, invc, e2 & 7);
            float s3 = __shfl_sync(0xffffffffu, invc, e3 & 7);
            float v0 = __ldg(&g_H[(size_t)(e0 >> 3) * 288 + (e0 & 7) * 32 + lane]);
            float v1 = __ldg(&g_H[(size_t)(e1 >> 3) * 288 + (e1 & 7) * 32 + lane]);
            float v2 = __ldg(&g_H[(size_t)(e2 >> 3) * 288 + (e2 & 7) * 32 + lane]);
            float v3 = __ldg(&g_H[(size_t)(e3 >> 3) * 288 + (e3 & 7) * 32 + lane]);
            acc += v0 * s0 + v1 * s1 + v2 * s2 + v3 * s3;
        }
        for (; k < nb; k++) {
            int e0 = __shfl_sync(0xffffffffu, id, k);
            float s0 = __shfl_sync(0xffffffffu, invc, e0 & 7);
            acc += __ldg(&g_H[(size_t)(e0 >> 3) * 288 + (e0 & 7) * 32 + lane]) * s0;
        }
        i += nb;
    }
    float z = bias2[lane] + g_H[(size_t)gw * 288 + 256 + lane] + acc;
    out[gw * 32 + lane] = 1.0f / (1.0f + __expf(-z));
}

// ---------------- launch ----------------
extern "C" void kernel_launch(void* const* d_in, const int* in_sizes, int n_in,
                              void* d_out, int out_size) {
    const void*  ei    = d_in[0];
    const void*  et    = d_in[1];
    const float* emb   = (const float*)d_in[2];
    const float* W1    = (const float*)d_in[3];
    const float* root1 = (const float*)d_in[4];
    const float* bias1 = (const float*)d_in[5];
    const float* W2    = (const float*)d_in[6];
    const float* root2 = (const float*)d_in[7];
    const float* bias2 = (const float*)d_in[8];
    float*       out   = (float*)d_out;

    // Try to fork CSR build onto a side stream so it overlaps GEMM1.
    cudaStream_t s2 = 0;
    cudaEvent_t evA = 0, evB = 0;
    bool fork = (cudaStreamCreateWithFlags(&s2, cudaStreamNonBlocking) == cudaSuccess);
    if (fork) fork = (cudaEventCreateWithFlags(&evA, cudaEventDisableTiming) == cudaSuccess);
    if (fork) fork = (cudaEventCreateWithFlags(&evB, cudaEventDisableTiming) == cudaSuccess);
    cudaStream_t cs = fork ? s2 : (cudaStream_t)0;
    if (fork) { cudaEventRecord(evA, 0); cudaStreamWaitEvent(s2, evA, 0); }

    // CSR chain
    k_detect<<<1, 256, 0, cs>>>((const int*)ei, (const int*)et);
    k_zero_cnt<<<(NN * RR + 255) / 256, 256, 0, cs>>>();
    k_count<<<(EE + 255) / 256, 256, 0, cs>>>(ei, et);
    k_scan1<<<196, 512, 0, cs>>>();
    k_scan2<<<1, 32, 0, cs>>>(196);
    k_scan3<<<196, 512, 0, cs>>>();
    k_scatter<<<(EE + 255) / 256, 256, 0, cs>>>(ei, et);
    if (fork) cudaEventRecord(evB, s2);

    // layer-1 GEMM (independent of CSR) on default stream
    dim3 g1((NN + 127) / 128, 3);
    k_gemm<128, 64, 192, 2, false><<<g1, 256>>>(emb, W1, root1);

    if (fork) cudaStreamWaitEvent(0, evB, 0);

    k_agg1<<<(NN + 7) / 8, 256>>>(bias1);

    // layer 2
    dim3 g2((NN + 127) / 128, 3);
    k_gemm<64, 32, 96, 4, true><<<g2, 256>>>(nullptr, W2, root2);
    k_agg2<<<(NN + 7) / 8, 256>>>(bias2, out);
}

// round 4
// speedup vs baseline: 1.2348x; 1.1969x over previous
#include <cuda_runtime.h>
#include <cuda_fp16.h>
#include <cstdint>

#define NN   100000
#define RR   8
#define EE   1600000
#define F0   128
#define F1   64
#define F2   32
#define LDO1 576   /* 8*64 + 64 (root) */
#define LDO2 288   /* 8*32 + 32 (root) */

// ---------------- scratch (device globals: allocation-free) ----------------
__device__ __half g_Hh[(size_t)NN * LDO1]; // 115 MB fp16, reused as H2 [NN,288]
__device__ float g_out1[NN * F1];          // layer-1 output (fp32)
__device__ int   g_cnt[NN * RR];
__device__ float g_invc[NN * RR];
__device__ int   g_rowptr[NN + 1];
__device__ int   g_cursor[NN];
__device__ int   g_csr[EE];                // packed src*8+rel
__device__ int   g_blocksums[256];
__device__ int   g_is64[2];                // dtype flags: edge_index, edge_type

// ---------------- dtype detection ----------------
__global__ void k_detect(const int* __restrict__ ei, const int* __restrict__ et) {
    __shared__ int nz0, nz1;
    if (threadIdx.x == 0) { nz0 = 0; nz1 = 0; }
    __syncthreads();
    for (int i = threadIdx.x; i < 1024; i += blockDim.x) {
        if (ei[2 * i + 1] != 0) atomicOr(&nz0, 1);
        if (et[2 * i + 1] != 0) atomicOr(&nz1, 1);
    }
    __syncthreads();
    if (threadIdx.x == 0) { g_is64[0] = nz0 ? 0 : 1; g_is64[1] = nz1 ? 0 : 1; }
}

__device__ __forceinline__ int readIdx(const void* p, int is64, int i) {
    return is64 ? (int)((const long long*)p)[i] : ((const int*)p)[i];
}

// ---------------- CSR build ----------------
__global__ void k_zero_cnt() {
    int i = blockIdx.x * blockDim.x + threadIdx.x;
    if (i < NN * RR) g_cnt[i] = 0;
}

__global__ void k_count(const void* __restrict__ ei, const void* __restrict__ et) {
    int e = blockIdx.x * blockDim.x + threadIdx.x;
    if (e >= EE) return;
    int dst = readIdx(ei, g_is64[0], EE + e);
    int rel = readIdx(et, g_is64[1], e) & 7;
    if ((unsigned)dst >= NN) dst = 0;
    atomicAdd(&g_cnt[dst * RR + rel], 1);
}

__global__ void k_scan1() {
    __shared__ int s[512];
    int t = threadIdx.x;
    int i = blockIdx.x * 512 + t;
    int d = 0;
    if (i < NN) {
        #pragma unroll
        for (int r = 0; r < RR; r++) d += g_cnt[i * RR + r];
    }
    s[t] = d;
    __syncthreads();
    for (int off = 256; off > 0; off >>= 1) {
        if (t < off) s[t] += s[t + off];
        __syncthreads();
    }
    if (t == 0) g_blocksums[blockIdx.x] = s[0];
}

// parallel exclusive scan of the 196 block sums (single block)
__global__ void k_scan2() {
    __shared__ int s[256];
    int t = threadIdx.x;
    int v = (t < 196) ? g_blocksums[t] : 0;
    s[t] = v;
    __syncthreads();
    for (int off = 1; off < 256; off <<= 1) {
        int u = (t >= off) ? s[t - off] : 0;
        __syncthreads();
        s[t] += u;
        __syncthreads();
    }
    if (t < 196) g_blocksums[t] = s[t] - v;
}

__global__ void k_scan3() {
    __shared__ int s[512];
    int t = threadIdx.x;
    int i = blockIdx.x * 512 + t;
    int d = 0;
    if (i < NN) {
        #pragma unroll
        for (int r = 0; r < RR; r++) d += g_cnt[i * RR + r];
    }
    s[t] = d;
    __syncthreads();
    for (int off = 1; off < 512; off <<= 1) {
        int v = (t >= off) ? s[t - off] : 0;
        __syncthreads();
        s[t] += v;
        __syncthreads();
    }
    if (i < NN) {
        int rp = g_blocksums[blockIdx.x] + s[t] - d;   // exclusive
        g_rowptr[i] = rp;
        g_cursor[i] = rp;
        #pragma unroll
        for (int r = 0; r < RR; r++) {
            int c = g_cnt[i * RR + r];
            g_invc[i * RR + r] = 1.0f / (float)(c > 0 ? c : 1);
        }
    }
    if (blockIdx.x == 0 && t == 0) g_rowptr[NN] = EE;
}

__global__ void k_scatter(const void* __restrict__ ei, const void* __restrict__ et) {
    int e = blockIdx.x * blockDim.x + threadIdx.x;
    if (e >= EE) return;
    int src = readIdx(ei, g_is64[0], e);
    int dst = readIdx(ei, g_is64[0], EE + e);
    int rel = readIdx(et, g_is64[1], e) & 7;
    if ((unsigned)src >= NN) src = 0;
    if ((unsigned)dst >= NN) dst = 0;
    int pos = atomicAdd(&g_cursor[dst], 1);
    if ((unsigned)pos < EE) g_csr[pos] = src * RR + rel;
}

// ---------------- tf32 GEMM: H(fp16) = A @ [W_0 .. W_7 | root] ----------------
__device__ __forceinline__ float to_tf32(float x) {
    uint32_t u;
    asm("cvt.rna.tf32.f32 %0, %1;" : "=r"(u) : "f"(x));
    return __uint_as_float(u);
}

__device__ __forceinline__ void mma_tf32(float* c, const uint32_t* a, const uint32_t* b) {
    asm volatile(
        "mma.sync.aligned.m16n8k8.row.col.f32.tf32.tf32.f32 "
        "{%0,%1,%2,%3},{%4,%5,%6,%7},{%8,%9},{%0,%1,%2,%3};"
        : "+f"(c[0]), "+f"(c[1]), "+f"(c[2]), "+f"(c[3])
        : "r"(a[0]), "r"(a[1]), "r"(a[2]), "r"(a[3]), "r"(b[0]), "r"(b[1]));
}

template <int KT, int FOUT, int BN, int WARPM, bool A_IS_OUT1>
__global__ void __launch_bounds__(256) k_gemm(
    const float* __restrict__ Aext,
    const float* __restrict__ Wrel,   // [8][KT][FOUT]
    const float* __restrict__ Wroot)  // [KT][FOUT]
{
    constexpr int BM = 128, KC = 32;
    constexpr int AS = KC + 4;
    constexpr int BS = BN + 8;
    constexpr int WARPN = 8 / WARPM;
    constexpr int WMROWS = BM / WARPM;
    constexpr int MF = WMROWS / 16;
    constexpr int WN = BN / WARPN;
    constexpr int NF = WN / 8;
    constexpr int LDO = 9 * FOUT;
    constexpr int NCH = KT / KC;

    __shared__ float As[BM * AS];
    __shared__ float Bs[KC * BS];

    const float* A = A_IS_OUT1 ? (const float*)g_out1 : Aext;
    int tid = threadIdx.x;
    int m0 = blockIdx.x * BM;
    int n0 = blockIdx.y * BN;

    int wid = tid >> 5, lane = tid & 31;
    int wm = wid % WARPM, wn = wid / WARPM;
    int grp = lane >> 2, tig = lane & 3;

    float c[MF][NF][4];
    #pragma unroll
    for (int mf = 0; mf < MF; mf++)
        #pragma unroll
        for (int nf = 0; nf < NF; nf++)
            #pragma unroll
            for (int q = 0; q < 4; q++) c[mf][nf][q] = 0.f;

    for (int ch = 0; ch < NCH; ch++) {
        int k0 = ch * KC;
        #pragma unroll
        for (int idx = tid; idx < BM * KC / 4; idx += 256) {
            int r  = idx >> 3;
            int c4 = (idx & 7) * 4;
            float4 v = make_float4(0.f, 0.f, 0.f, 0.f);
            if (m0 + r < NN) v = *(const float4*)(A + (size_t)(m0 + r) * KT + k0 + c4);
            v.x = to_tf32(v.x); v.y = to_tf32(v.y); v.z = to_tf32(v.z); v.w = to_tf32(v.w);
            *(float4*)(As + r * AS + c4) = v;
        }
        #pragma unroll
        for (int idx = tid; idx < KC * BN / 4; idx += 256) {
            int k  = idx / (BN / 4);
            int c4 = (idx % (BN / 4)) * 4;
            int gc = n0 + c4;
            int rel = gc / FOUT;
            int within = gc % FOUT;
            const float* src = (rel < 8)
                ? (Wrel + ((size_t)rel * KT + k0 + k) * FOUT + within)
                : (Wroot + (size_t)(k0 + k) * FOUT + within);
            float4 v = *(const float4*)src;
            v.x = to_tf32(v.x); v.y = to_tf32(v.y); v.z = to_tf32(v.z); v.w = to_tf32(v.w);
            *(float4*)(Bs + k * BS + c4) = v;
        }
        __syncthreads();

        #pragma unroll
        for (int kk = 0; kk < KC / 8; kk++) {
            int kb = kk * 8;
            uint32_t a[MF][4];
            #pragma unroll
            for (int mf = 0; mf < MF; mf++) {
                const float* p = As + (wm * WMROWS + mf * 16 + grp) * AS + kb + tig;
                a[mf][0] = __float_as_uint(p[0]);
                a[mf][1] = __float_as_uint(p[8 * AS]);
                a[mf][2] = __float_as_uint(p[4]);
                a[mf][3] = __float_as_uint(p[8 * AS + 4]);
            }
            uint32_t b[NF][2];
            #pragma unroll
            for (int nf = 0; nf < NF; nf++) {
                const float* p = Bs + (kb + tig) * BS + wn * WN + nf * 8 + grp;
                b[nf][0] = __float_as_uint(p[0]);
                b[nf][1] = __float_as_uint(p[4 * BS]);
            }
            #pragma unroll
            for (int mf = 0; mf < MF; mf++)
                #pragma unroll
                for (int nf = 0; nf < NF; nf++)
                    mma_tf32(c[mf][nf], a[mf], b[nf]);
        }
        __syncthreads();
    }

    // store fp16
    #pragma unroll
    for (int mf = 0; mf < MF; mf++)
        #pragma unroll
        for (int nf = 0; nf < NF; nf++) {
            int row = m0 + wm * WMROWS + mf * 16 + grp;
            int col = n0 + wn * WN + nf * 8 + tig * 2;   // even
            __half* p = g_Hh + (size_t)row * LDO + col;
            if (row < NN)
                *(__half2*)p = __floats2half2_rn(c[mf][nf][0], c[mf][nf][1]);
            if (row + 8 < NN)
                *(__half2*)(p + (size_t)8 * LDO) = __floats2half2_rn(c[mf][nf][2], c[mf][nf][3]);
        }
}

// ---------------- aggregation (warp per dst node, no atomics) ----------------
__global__ void __launch_bounds__(256) k_agg1(const float* __restrict__ bias1) {
    int gw = (blockIdx.x * blockDim.x + threadIdx.x) >> 5;
    int lane = threadIdx.x & 31;
    if (gw >= NN) return;
    int beg = g_rowptr[gw], end = g_rowptr[gw + 1];
    float invc = (lane < RR) ? g_invc[gw * RR + lane] : 0.f;
    const __half2* Hp = (const __half2*)g_Hh;   // row stride 288 half2, rel stride 32
    float acc0 = 0.f, acc1 = 0.f;
    int i = beg;
    while (i < end) {
        int nb = min(32, end - i);
        int id = (lane < nb) ? g_csr[i + lane] : 0;
        #pragma unroll 4
        for (int k = 0; k < nb; k++) {
            int e = __shfl_sync(0xffffffffu, id, k);
            float s = __shfl_sync(0xffffffffu, invc, e & 7);
            __half2 v = __ldg(&Hp[(size_t)(e >> 3) * 288 + (e & 7) * 32 + lane]);
            float2 f = __half22float2(v);
            acc0 += f.x * s;
            acc1 += f.y * s;
        }
        i += nb;
    }
    float2 rt = __half22float2(Hp[(size_t)gw * 288 + 256 + lane]);  // root block
    float2 bs = ((const float2*)bias1)[lane];
    float o0 = bs.x + rt.x + acc0;
    float o1 = bs.y + rt.y + acc1;
    ((float2*)g_out1)[gw * 32 + lane] = make_float2(fmaxf(o0, 0.f), fmaxf(o1, 0.f));
}

// layer 2: half-warp per edge (lanes 0-15 edge k, 16-31 edge k+1)
__global__ void __launch_bounds__(256) k_agg2(const float* __restrict__ bias2,
                                              float* __restrict__ out) {
    int gw = (blockIdx.x * blockDim.x + threadIdx.x) >> 5;
    int lane = threadIdx.x & 31;
    if (gw >= NN) return;
    int beg = g_rowptr[gw], end = g_rowptr[gw + 1];
    float invc = (lane < RR) ? g_invc[gw * RR + lane] : 0.f;
    const __half2* Hp = (const __half2*)g_Hh;   // row stride 144 half2, rel stride 16
    int sub = lane >> 4;        // which edge of the pair
    int cp  = lane & 15;        // column pair
    float acc0 = 0.f, acc1 = 0.f;
    int i = beg;
    while (i < end) {
        int nb = min(32, end - i);
        int id = (lane < nb) ? g_csr[i + lane] : 0;
        int k = 0;
        #pragma unroll 4
        for (; k + 2 <= nb; k += 2) {
            int e = __shfl_sync(0xffffffffu, id, k + sub);
            float s = __shfl_sync(0xffffffffu, invc, e & 7);
            __half2 v = __ldg(&Hp[(size_t)(e >> 3) * 144 + (e & 7) * 16 + cp]);
            float2 f = __half22float2(v);
            acc0 += f.x * s;
            acc1 += f.y * s;
        }
        if (k < nb) {   // tail: single edge, sub==1 half contributes zero
            int e = __shfl_sync(0xffffffffu, id, k);
            float s = __shfl_sync(0xffffffffu, invc, e & 7);
            s = sub ? 0.f : s;
            __half2 v = __ldg(&Hp[(size_t)(e >> 3) * 144 + (e & 7) * 16 + cp]);
            float2 f = __half22float2(v);
            acc0 += f.x * s;
            acc1 += f.y * s;
        }
        i += nb;
    }
    acc0 += __shfl_down_sync(0xffffffffu, acc0, 16);
    acc1 += __shfl_down_sync(0xffffffffu, acc1, 16);
    if (sub == 0) {
        float2 rt = __half22float2(Hp[(size_t)gw * 144 + 128 + cp]);
        float2 bs = ((const float2*)bias2)[cp];
        float z0 = bs.x + rt.x + acc0;
        float z1 = bs.y + rt.y + acc1;
        ((float2*)out)[gw * 16 + cp] =
            make_float2(1.0f / (1.0f + __expf(-z0)), 1.0f / (1.0f + __expf(-z1)));
    }
}

// ---------------- launch ----------------
extern "C" void kernel_launch(void* const* d_in, const int* in_sizes, int n_in,
                              void* d_out, int out_size) {
    const void*  ei    = d_in[0];
    const void*  et    = d_in[1];
    const float* emb   = (const float*)d_in[2];
    const float* W1    = (const float*)d_in[3];
    const float* root1 = (const float*)d_in[4];
    const float* bias1 = (const float*)d_in[5];
    const float* W2    = (const float*)d_in[6];
    const float* root2 = (const float*)d_in[7];
    const float* bias2 = (const float*)d_in[8];
    float*       out   = (float*)d_out;

    // Fork CSR build onto a side stream so it overlaps GEMM1.
    cudaStream_t s2 = 0;
    cudaEvent_t evA = 0, evB = 0;
    bool fork = (cudaStreamCreateWithFlags(&s2, cudaStreamNonBlocking) == cudaSuccess);
    if (fork) fork = (cudaEventCreateWithFlags(&evA, cudaEventDisableTiming) == cudaSuccess);
    if (fork) fork = (cudaEventCreateWithFlags(&evB, cudaEventDisableTiming) == cudaSuccess);
    cudaStream_t cs = fork ? s2 : (cudaStream_t)0;
    if (fork) { cudaEventRecord(evA, 0); cudaStreamWaitEvent(s2, evA, 0); }

    // CSR chain
    k_detect<<<1, 256, 0, cs>>>((const int*)ei, (const int*)et);
    k_zero_cnt<<<(NN * RR + 255) / 256, 256, 0, cs>>>();
    k_count<<<(EE + 255) / 256, 256, 0, cs>>>(ei, et);
    k_scan1<<<196, 512, 0, cs>>>();
    k_scan2<<<1, 256, 0, cs>>>();
    k_scan3<<<196, 512, 0, cs>>>();
    k_scatter<<<(EE + 255) / 256, 256, 0, cs>>>(ei, et);
    if (fork) cudaEventRecord(evB, s2);

    // layer-1 GEMM (independent of CSR) on default stream
    dim3 g1((NN + 127) / 128, 3);
    k_gemm<128, 64, 192, 2, false><<<g1, 256>>>(emb, W1, root1);

    if (fork) cudaStreamWaitEvent(0, evB, 0);

    k_agg1<<<(NN + 7) / 8, 256>>>(bias1);

    // layer 2
    dim3 g2((NN + 127) / 128, 3);
    k_gemm<64, 32, 96, 4, true><<<g2, 256>>>(nullptr, W2, root2);
    k_agg2<<<(NN + 7) / 8, 256>>>(bias2, out);
}